// round 16
// baseline (speedup 1.0000x reference)
#include <cuda_runtime.h>
#include <cuda_fp16.h>
#include <cstdint>

// B=32, P=512, S=1024, H=1024, R=256, K3=3072
// out[M=16384,256] = feats[M,3072] @ W^T + bias
// R16: FULLY FUSED A-path. g_feats eliminated; each GEMM CTA gathers hidden
// rows and builds its A chunk (head/tail/head*tail) directly into SMEM,
// sliced into four 4-column passes interleaved with the 4 k-steps (16
// transient regs, gather LDGs covered by an MMA block each). B ring and all
// GEMM geometry identical to the proven R12/R15 config (512 thr, 16 warps
// 4x4, warp tile 32x64, KC=64, 3-stage cp.async.ca ring, 1 barrier/chunk).

#define THREADS 512

__device__ __half g_Wh[256 * 3072];   // W as fp16 (tiny standalone prologue)

static __device__ __forceinline__ uint32_t smem_u32(const void* p) {
    uint32_t a;
    asm("{ .reg .u64 t; cvta.to.shared.u64 t, %1; cvt.u32.u64 %0, t; }"
        : "=r"(a) : "l"(p));
    return a;
}
static __device__ __forceinline__ void ldsm4(uint32_t* r, uint32_t addr) {
    asm volatile("ldmatrix.sync.aligned.m8n8.x4.shared.b16 {%0,%1,%2,%3}, [%4];"
                 : "=r"(r[0]), "=r"(r[1]), "=r"(r[2]), "=r"(r[3]) : "r"(addr));
}
static __device__ __forceinline__ void mma_f16(float* d, const uint32_t* a,
                                               const uint32_t* b) {
    asm volatile("mma.sync.aligned.m16n8k16.row.col.f32.f16.f16.f32 "
                 "{%0,%1,%2,%3}, {%4,%5,%6,%7}, {%8,%9}, {%0,%1,%2,%3};"
                 : "+f"(d[0]), "+f"(d[1]), "+f"(d[2]), "+f"(d[3])
                 : "r"(a[0]), "r"(a[1]), "r"(a[2]), "r"(a[3]),
                   "r"(b[0]), "r"(b[1]));
}
static __device__ __forceinline__ void cpasync16(uint32_t dst, const void* src) {
    asm volatile("cp.async.ca.shared.global [%0], [%1], 16;"
                 :: "r"(dst), "l"(src) : "memory");
}
static __device__ __forceinline__ uint32_t h2bits(__half2 h) {
    return *reinterpret_cast<uint32_t*>(&h);
}
static __device__ __forceinline__ uint2 pack4(float x, float y, float z, float w) {
    return make_uint2(h2bits(__float22half2_rn(make_float2(x, y))),
                      h2bits(__float22half2_rn(make_float2(z, w))));
}

// SMEM: A double buffer (2 x 128x72 fp16) + B 3-stage ring (3 x 256x72 fp16)
#define LDA 72
#define PITCH (LDA * 2)                       // 144 B (conflict-free ldsm)
#define A_BUF_BYTES (128 * PITCH)             // 18432
#define OFF_B0 (2 * A_BUF_BYTES)              // 36864
#define B_STAGE (256 * PITCH)                 // 36864
#define SMEM_BYTES (OFF_B0 + 3 * B_STAGE)     // 147456

// ---- prologue kernel: W f32 -> fp16 ----
__global__ void w_cvt_kernel(const float* __restrict__ Wg) {
    const int i = blockIdx.x * blockDim.x + threadIdx.x;
    if (i >= 256 * 3072 / 4) return;
    float4 v = reinterpret_cast<const float4*>(Wg)[i];
    reinterpret_cast<uint2*>(g_Wh)[i] = pack4(v.x, v.y, v.z, v.w);
}

// ---- fused gather+build+GEMM: CTA 128(M) x 256(N), 16 warps (4x4) ----
__global__ void __launch_bounds__(THREADS, 1)
gr_fused_kernel(const int*   __restrict__ pairs32,
                const float* __restrict__ hidden,
                const float* __restrict__ bias,
                float*       __restrict__ out)
{
    constexpr int KC  = 64;
    constexpr int NCH = 3072 / KC;   // 48

    extern __shared__ char dsm[];
    const uint32_t smb = smem_u32(dsm);
    __shared__ float sBias[256];
    __shared__ int4  sIdx[128];
    __shared__ int   sIs64;

    const int t    = threadIdx.x;
    const int lane = t & 31;
    const int w    = t >> 5;
    const int wm   = w >> 2;       // 0..3 : 32-row m group
    const int wn   = w & 3;        // 0..3 : 64-col n group
    const int row0 = blockIdx.x * 128;
    const int b    = row0 >> 9;

    if (t == 0) {   // int64 pairs -> all odd 32-bit words zero (indices < 1024)
        int a = 0;
#pragma unroll
        for (int i = 1; i < 128; i += 2) a |= pairs32[i];
        sIs64 = (a == 0);
    }
    if (t < 256) sBias[t] = bias[t];
    __syncthreads();
    if (t < 128) {
        const size_t pidx = (size_t)b * 512 + (row0 & 511) + t;
        if (sIs64) {
            const long long* p64 = reinterpret_cast<const long long*>(pairs32) + pidx * 4;
            sIdx[t] = make_int4((int)p64[0], (int)p64[1], (int)p64[2], (int)p64[3]);
        } else {
            sIdx[t] = reinterpret_cast<const int4*>(pairs32)[pidx];
        }
    }
    __syncthreads();

    // ---- A production mapping: 4 thr/row, 16 cols each, in 4x 4-col passes
    const int arow  = t >> 2;
    const int acol0 = (t & 3) << 4;             // 0,16,32,48
    const int4 id   = sIdx[arow];
    const float* hb = hidden + (size_t)b * (size_t)(1024 * 1024);
    const float4* q0 = reinterpret_cast<const float4*>(hb + (size_t)id.x * 1024);
    const float4* q1 = reinterpret_cast<const float4*>(hb + (size_t)id.y * 1024);
    const float4* q2 = reinterpret_cast<const float4*>(hb + (size_t)id.z * 1024);
    const float4* q3 = reinterpret_cast<const float4*>(hb + (size_t)id.w * 1024);
    const uint32_t aProdOff = arow * PITCH + acol0 * 2;   // byte off in A buf

    // B staging (cp.async): 2 thr/row, 32 cols (64 B) each
    const int brow = t >> 1;
    const int bk   = (t & 1) << 5;
    const __half* bsrc = g_Wh + (size_t)brow * 3072 + bk;
    const uint32_t bdst = brow * PITCH + bk * 2;

    auto prefetchB = [&](int c) {
        const uint32_t buf = smb + OFF_B0 + (c % 3) * B_STAGE;
        const __half* bs = bsrc + c * KC;
#pragma unroll
        for (int i = 0; i < 4; ++i) cpasync16(buf + bdst + i * 16, bs + i * 8);
        asm volatile("cp.async.commit_group;");
    };

    // build 4 cols of A for chunk cn, pass p, from loaded float4s
    auto buildA = [&](int cn, int p, float4 a, float4 d, float4 e, float4 f) {
        const int s = cn >> 4;                    // 0=head, 1=tail, 2=prod
        float hx = 0.5f*(a.x+d.x), hy = 0.5f*(a.y+d.y),
              hz = 0.5f*(a.z+d.z), hw = 0.5f*(a.w+d.w);
        float tx = 0.5f*(e.x+f.x), ty = 0.5f*(e.y+f.y),
              tz = 0.5f*(e.z+f.z), tw = 0.5f*(e.w+f.w);
        float vx = (s == 0) ? hx : (s == 1) ? tx : hx * tx;
        float vy = (s == 0) ? hy : (s == 1) ? ty : hy * ty;
        float vz = (s == 0) ? hz : (s == 1) ? tz : hz * tz;
        float vw = (s == 0) ? hw : (s == 1) ? tw : hw * tw;
        uint2 pk = pack4(vx, vy, vz, vw);
        const uint32_t dst = smb + (cn & 1) * A_BUF_BYTES + aProdOff + p * 8;
        asm volatile("st.shared.v2.b32 [%0], {%1, %2};"
                     :: "r"(dst), "r"(pk.x), "r"(pk.y));
    };

    float acc[2][8][4];
#pragma unroll
    for (int i = 0; i < 2; ++i)
#pragma unroll
        for (int j = 0; j < 8; ++j)
#pragma unroll
            for (int q = 0; q < 4; ++q) acc[i][j][q] = 0.f;

    const int lr = lane & 15;
    const int lh = (lane >> 4) << 3;
    const uint32_t aOff = (wm * 32 + lr) * PITCH + lh * 2;
    const uint32_t bOff = (wn * 64 + lr) * PITCH + lh * 2;

    // ---- prologue: B chunks 0,1 in flight; produce A(0) synchronously
    prefetchB(0);
    prefetchB(1);
    {
        const int f4b = (0 >> 4, 0);   // chunk 0: hk float4 base
        const int base = (0 & 15) * 16 + (acol0 >> 2);
#pragma unroll
        for (int p = 0; p < 4; ++p) {
            float4 a = q0[base + p], d = q1[base + p];
            float4 e = q2[base + p], f = q3[base + p];
            buildA(0, p, a, d, e, f);
        }
        (void)f4b;
    }

    for (int c = 0; c < NCH; ++c) {
        asm volatile("cp.async.wait_group 1;" ::: "memory");   // B chunk c ready
        __syncthreads();            // A(c) STS visible; B slot (c-1)%3 free
        if (c + 2 < NCH) prefetchB(c + 2);

        const uint32_t aBase = smb + (c & 1) * A_BUF_BYTES + aOff;
        const uint32_t bBase = smb + OFF_B0 + (c % 3) * B_STAGE + bOff;
        const bool produce = (c + 1 < NCH);
        const int  cn      = c + 1;
        const int  nbase   = (cn & 15) * 16 + (acol0 >> 2);   // float4 idx

#pragma unroll
        for (int kk = 0; kk < 4; ++kk) {
            // issue gather LDGs for A(c+1) pass kk (covered by this k-step)
            float4 ga, gd, ge, gf;
            if (produce) {
                ga = q0[nbase + kk]; gd = q1[nbase + kk];
                ge = q2[nbase + kk]; gf = q3[nbase + kk];
            }
            const uint32_t kb = kk * 32;
            uint32_t af[2][4], bf[8][2];
#pragma unroll
            for (int mt = 0; mt < 2; ++mt)
                ldsm4(af[mt], aBase + mt * 16 * PITCH + kb);
#pragma unroll
            for (int p = 0; p < 4; ++p) {
                uint32_t r[4];
                ldsm4(r, bBase + p * 16 * PITCH + kb);
                bf[2*p][0]   = r[0]; bf[2*p][1]   = r[2];
                bf[2*p+1][0] = r[1]; bf[2*p+1][1] = r[3];
            }
#pragma unroll
            for (int mt = 0; mt < 2; ++mt)
#pragma unroll
                for (int n8 = 0; n8 < 8; ++n8)
                    mma_f16(acc[mt][n8], af[mt], bf[n8]);
            // build + store the pass (gathers have had a full MMA block)
            if (produce) buildA(cn, kk, ga, gd, ge, gf);
        }
    }

    // ---- epilogue: bias + fp32 store ----
    const int g  = lane >> 2;
    const int tq = lane & 3;
#pragma unroll
    for (int mt = 0; mt < 2; ++mt) {
        const int r0g = row0 + wm * 32 + mt * 16 + g;
#pragma unroll
        for (int n8 = 0; n8 < 8; ++n8) {
            const int col = wn * 64 + n8 * 8 + tq * 2;
            const float bx = sBias[col], by = sBias[col + 1];
            float* o0 = out + (size_t)r0g * 256 + col;
            float* o1 = o0 + 8 * 256;
            *reinterpret_cast<float2*>(o0) =
                make_float2(acc[mt][n8][0] + bx, acc[mt][n8][1] + by);
            *reinterpret_cast<float2*>(o1) =
                make_float2(acc[mt][n8][2] + bx, acc[mt][n8][3] + by);
        }
    }
}

extern "C" void kernel_launch(void* const* d_in, const int* in_sizes, int n_in,
                              void* d_out, int out_size) {
    (void)in_sizes; (void)n_in; (void)out_size;
    const int*   pairs  = (const int*)  d_in[0];
    const float* hidden = (const float*)d_in[1];
    const float* W      = (const float*)d_in[2];
    const float* bias   = (const float*)d_in[3];
    float*       out    = (float*)d_out;

    static bool attr_set = false;
    if (!attr_set) {
        cudaFuncSetAttribute(gr_fused_kernel,
                             cudaFuncAttributeMaxDynamicSharedMemorySize, SMEM_BYTES);
        attr_set = true;
    }
    w_cvt_kernel<<<(256 * 3072 / 4 + 255) / 256, 256>>>(W);
    gr_fused_kernel<<<16384 / 128, THREADS, SMEM_BYTES>>>(pairs, hidden, bias, out);
}

// round 17
// speedup vs baseline: 1.5787x; 1.5787x over previous
#include <cuda_runtime.h>
#include <cuda_fp16.h>
#include <cstdint>

// B=32, P=512, S=1024, H=1024, R=256, K3=3072
// out[M=16384,256] = feats[M,3072] @ W^T + bias
// R17: R15/R12 proven config (decoupled feats; GEMM 512 thr, 16 warps 4x4,
// warp tile 32x64, KC=64, NSTAGE=3, cp.async.ca, 1 barrier/chunk) with
// micro-scheduling fixes only:
//  - k-step 0 fragment ldsm issued immediately post-barrier, cp.async
//    prefetch issued BEHIND them (critical-path issue priority)
//  - feats kernel at 512 threads (grid 1024)
// Fused A-path abandoned (falsified 3x: R6 ordering, R7 regs, R16 traffic).

#define THREADS 512

__device__ __half g_Wh[256 * 3072];            // W as fp16
__device__ __half g_feats[16384 * 3072];       // feats as fp16 (96 MB scratch)

static __device__ __forceinline__ uint32_t smem_u32(const void* p) {
    uint32_t a;
    asm("{ .reg .u64 t; cvta.to.shared.u64 t, %1; cvt.u32.u64 %0, t; }"
        : "=r"(a) : "l"(p));
    return a;
}
static __device__ __forceinline__ void ldsm4(uint32_t* r, uint32_t addr) {
    asm volatile("ldmatrix.sync.aligned.m8n8.x4.shared.b16 {%0,%1,%2,%3}, [%4];"
                 : "=r"(r[0]), "=r"(r[1]), "=r"(r[2]), "=r"(r[3]) : "r"(addr));
}
static __device__ __forceinline__ void mma_f16(float* d, const uint32_t* a,
                                               const uint32_t* b) {
    asm volatile("mma.sync.aligned.m16n8k16.row.col.f32.f16.f16.f32 "
                 "{%0,%1,%2,%3}, {%4,%5,%6,%7}, {%8,%9}, {%0,%1,%2,%3};"
                 : "+f"(d[0]), "+f"(d[1]), "+f"(d[2]), "+f"(d[3])
                 : "r"(a[0]), "r"(a[1]), "r"(a[2]), "r"(a[3]),
                   "r"(b[0]), "r"(b[1]));
}
static __device__ __forceinline__ void cpasync16(uint32_t dst, const void* src) {
    asm volatile("cp.async.ca.shared.global [%0], [%1], 16;"
                 :: "r"(dst), "l"(src) : "memory");
}
static __device__ __forceinline__ uint32_t h2bits(__half2 h) {
    return *reinterpret_cast<uint32_t*>(&h);
}
static __device__ __forceinline__ uint2 pack4(float x, float y, float z, float w) {
    return make_uint2(h2bits(__float22half2_rn(make_float2(x, y))),
                      h2bits(__float22half2_rn(make_float2(z, w))));
}

// SMEM per stage: A[128][72] + B[256][72] fp16, pitch 144 B (conflict-free)
#define LDA 72
#define PITCH (LDA * 2)
#define OFF_B (128 * PITCH)                   // 18432
#define STAGE_STRIDE (OFF_B + 256 * PITCH)    // 55296
#define NSTAGE 3
#define SMEM_BYTES (NSTAGE * STAGE_STRIDE)    // 165888

// ---- prologue: gather + feature build -> fp16 feats; also converts W ----
// 512 threads, 16 rows (warps) per block, grid 1024.
__global__ void __launch_bounds__(512)
feats_kernel(const int* __restrict__ pairs32, const float* __restrict__ hidden,
             const float* __restrict__ Wg) {
    __shared__ int sIs64;
    const int t    = threadIdx.x;
    const int lane = t & 31;
    const int wid  = t >> 5;

    if (blockIdx.x < 384) {   // fused W conversion: 384 blocks x 512 float4
        const int i = blockIdx.x * 512 + t;   // < 196608
        float4 v = reinterpret_cast<const float4*>(Wg)[i];
        reinterpret_cast<uint2*>(g_Wh)[i] = pack4(v.x, v.y, v.z, v.w);
    }

    if (t == 0) {   // int64 pairs -> all odd 32-bit words zero (indices < 1024)
        int a = 0;
#pragma unroll
        for (int i = 1; i < 128; i += 2) a |= pairs32[i];
        sIs64 = (a == 0);
    }
    __syncthreads();

    const int row = blockIdx.x * 16 + wid;
    const int b   = row >> 9;
    int4 id;
    if (sIs64) {
        const long long* p64 = reinterpret_cast<const long long*>(pairs32) + (size_t)row * 4;
        id = make_int4((int)p64[0], (int)p64[1], (int)p64[2], (int)p64[3]);
    } else {
        id = reinterpret_cast<const int4*>(pairs32)[row];
    }

    const float* hb = hidden + (size_t)b * (size_t)(1024 * 1024);
    const float4* x0 = reinterpret_cast<const float4*>(hb + (size_t)id.x * 1024);
    const float4* x1 = reinterpret_cast<const float4*>(hb + (size_t)id.y * 1024);
    const float4* x2 = reinterpret_cast<const float4*>(hb + (size_t)id.z * 1024);
    const float4* x3 = reinterpret_cast<const float4*>(hb + (size_t)id.w * 1024);
    uint2* fr = reinterpret_cast<uint2*>(g_feats + (size_t)row * 3072);

#pragma unroll
    for (int j = 0; j < 8; ++j) {
        const int i = lane + j * 32;
        float4 a = x0[i], d = x1[i], e = x2[i], f = x3[i];
        float hx = 0.5f*(a.x+d.x), hy = 0.5f*(a.y+d.y),
              hz = 0.5f*(a.z+d.z), hw = 0.5f*(a.w+d.w);
        float tx = 0.5f*(e.x+f.x), ty = 0.5f*(e.y+f.y),
              tz = 0.5f*(e.z+f.z), tw = 0.5f*(e.w+f.w);
        fr[i]       = pack4(hx, hy, hz, hw);
        fr[i + 256] = pack4(tx, ty, tz, tw);
        fr[i + 512] = pack4(hx*tx, hy*ty, hz*tz, hw*tw);
    }
}

// ---- main GEMM: CTA 128(M) x 256(N), 16 warps (4x4), warp tile 32x64 ----
__global__ void __launch_bounds__(THREADS, 1)
gr_gemm_kernel(const float* __restrict__ bias, float* __restrict__ out)
{
    constexpr int KC  = 64;
    constexpr int NCH = 3072 / KC;   // 48

    extern __shared__ char dsm[];
    const uint32_t smb = smem_u32(dsm);
    __shared__ float sBias[256];

    const int t    = threadIdx.x;
    const int lane = t & 31;
    const int w    = t >> 5;
    const int wm   = w >> 2;       // 0..3 : 32-row m group
    const int wn   = w & 3;        // 0..3 : 64-col n group
    const int row0 = blockIdx.x * 128;

    if (t < 256) sBias[t] = bias[t];

    // staging (512 thr): A 4 thr/row x 16 cols (32 B), B 2 thr/row x 32 cols (64 B)
    const int arow = t >> 2;
    const int ak   = (t & 3) << 4;
    const __half* asrc = g_feats + (size_t)(row0 + arow) * 3072 + ak;
    const uint32_t adst = arow * PITCH + ak * 2;
    const int brow = t >> 1;
    const int bk   = (t & 1) << 5;
    const __half* bsrc = g_Wh + (size_t)brow * 3072 + bk;
    const uint32_t bdst = OFF_B + brow * PITCH + bk * 2;

    auto prefetch = [&](int c) {
        const uint32_t buf = smb + (c % NSTAGE) * STAGE_STRIDE;
        const __half* as = asrc + c * KC;
        const __half* bs = bsrc + c * KC;
#pragma unroll
        for (int i = 0; i < 2; ++i) cpasync16(buf + adst + i * 16, as + i * 8);
#pragma unroll
        for (int i = 0; i < 4; ++i) cpasync16(buf + bdst + i * 16, bs + i * 8);
        asm volatile("cp.async.commit_group;");
    };

    float acc[2][8][4];
#pragma unroll
    for (int i = 0; i < 2; ++i)
#pragma unroll
        for (int j = 0; j < 8; ++j)
#pragma unroll
            for (int q = 0; q < 4; ++q) acc[i][j][q] = 0.f;

    const int lr = lane & 15;
    const int lh = (lane >> 4) << 3;
    const uint32_t aOff = (wm * 32 + lr) * PITCH + lh * 2;
    const uint32_t bOff = OFF_B + (wn * 64 + lr) * PITCH + lh * 2;

    prefetch(0);
    prefetch(1);

    for (int c = 0; c < NCH; ++c) {
        asm volatile("cp.async.wait_group 1;" ::: "memory");   // chunk c ready
        __syncthreads();                     // + slot (c-1)%3 free

        const uint32_t base  = smb + (c % NSTAGE) * STAGE_STRIDE;
        const uint32_t aBase = base + aOff;
        const uint32_t bBase = base + bOff;

        // k-step 0 fragment loads FIRST (critical path), cp.async behind them
        uint32_t af[2][4], bf[8][2];
#pragma unroll
        for (int mt = 0; mt < 2; ++mt)
            ldsm4(af[mt], aBase + mt * 16 * PITCH);
#pragma unroll
        for (int p = 0; p < 4; ++p) {
            uint32_t r[4];
            ldsm4(r, bBase + p * 16 * PITCH);
            bf[2*p][0]   = r[0]; bf[2*p][1]   = r[2];
            bf[2*p+1][0] = r[1]; bf[2*p+1][1] = r[3];
        }

        if (c + 2 < NCH) prefetch(c + 2);    // writes slot (c-1)%3, post-sync

#pragma unroll
        for (int kk = 0; kk < 4; ++kk) {
            if (kk > 0) {
                const uint32_t kb = kk * 32;
#pragma unroll
                for (int mt = 0; mt < 2; ++mt)
                    ldsm4(af[mt], aBase + mt * 16 * PITCH + kb);
#pragma unroll
                for (int p = 0; p < 4; ++p) {
                    uint32_t r[4];
                    ldsm4(r, bBase + p * 16 * PITCH + kb);
                    bf[2*p][0]   = r[0]; bf[2*p][1]   = r[2];
                    bf[2*p+1][0] = r[1]; bf[2*p+1][1] = r[3];
                }
            }
#pragma unroll
            for (int mt = 0; mt < 2; ++mt)
#pragma unroll
                for (int n8 = 0; n8 < 8; ++n8)
                    mma_f16(acc[mt][n8], af[mt], bf[n8]);
        }
    }

    // ---- epilogue: bias + fp32 store ----
    const int g  = lane >> 2;
    const int tq = lane & 3;
#pragma unroll
    for (int mt = 0; mt < 2; ++mt) {
        const int r0g = row0 + wm * 32 + mt * 16 + g;
#pragma unroll
        for (int n8 = 0; n8 < 8; ++n8) {
            const int col = wn * 64 + n8 * 8 + tq * 2;
            const float bx = sBias[col], by = sBias[col + 1];
            float* o0 = out + (size_t)r0g * 256 + col;
            float* o1 = o0 + 8 * 256;
            *reinterpret_cast<float2*>(o0) =
                make_float2(acc[mt][n8][0] + bx, acc[mt][n8][1] + by);
            *reinterpret_cast<float2*>(o1) =
                make_float2(acc[mt][n8][2] + bx, acc[mt][n8][3] + by);
        }
    }
}

extern "C" void kernel_launch(void* const* d_in, const int* in_sizes, int n_in,
                              void* d_out, int out_size) {
    (void)in_sizes; (void)n_in; (void)out_size;
    const int*   pairs  = (const int*)  d_in[0];
    const float* hidden = (const float*)d_in[1];
    const float* W      = (const float*)d_in[2];
    const float* bias   = (const float*)d_in[3];
    float*       out    = (float*)d_out;

    static bool attr_set = false;
    if (!attr_set) {
        cudaFuncSetAttribute(gr_gemm_kernel,
                             cudaFuncAttributeMaxDynamicSharedMemorySize, SMEM_BYTES);
        attr_set = true;
    }
    feats_kernel<<<16384 / 16, 512>>>(pairs, hidden, W);
    gr_gemm_kernel<<<16384 / 128, THREADS, SMEM_BYTES>>>(bias, out);
}